// round 2
// baseline (speedup 1.0000x reference)
#include <cuda_runtime.h>
#include <cuda_bf16.h>
#include <cstdint>

#define TPB 512
#define MAXL 16

__global__ void __launch_bounds__(TPB)
rejection_sample_kernel(
    const float* __restrict__ draft_probs,    // [NT, V]
    const float* __restrict__ target_probs,   // [NT, V]
    const float* __restrict__ uniform_probs,  // [NT]
    const int*   __restrict__ draft_token_ids,// [NT]
    const int*   __restrict__ cu,             // [B]
    const int*   __restrict__ bonus,          // [B]
    float*       __restrict__ out,            // [B, L+1]  (float32 output buffer)
    int V, int NT, int L)
{
    const int b   = blockIdx.x;
    const int tid = threadIdx.x;

    __shared__ int   s_dids[MAXL];
    __shared__ float s_tp[MAXL], s_dp[MAXL], s_u[MAXL];
    __shared__ int   s_last, s_rejected, s_write_col, s_prev;
    __shared__ int   s_rec;
    __shared__ unsigned long long s_warp[TPB / 32];

    const int prev   = (b == 0) ? 0 : cu[b - 1];
    const int ndraft = cu[b] - prev;
    const int n      = ndraft < L ? ndraft : L;

    // Parallel gather of per-position values.
    if (tid < n && n > 0) {
        long long gidx = (long long)(prev + tid);
        int d = __ldg(&draft_token_ids[gidx]);
        s_dids[tid] = d;
        s_tp[tid] = __ldg(&target_probs[gidx * (long long)V + d]);
        s_dp[tid] = __ldg(&draft_probs [gidx * (long long)V + d]);
        s_u [tid] = __ldg(&uniform_probs[gidx]);
    }
    __syncthreads();

    // Sequential acceptance scan (pure arithmetic on shared values).
    if (tid == 0) {
        float pi = 1.0f, U = 1.0f;
        int last = -1;
        for (int i = 0; i < n; i++) {
            float dp = s_dp[i];
            float r  = (dp > 0.0f) ? (s_tp[i] / dp) : 1.0f;
            pi = fminf(pi * r, 1.0f);
            U  = U * s_u[i];
            if ((dp > 0.0f) && (pi >= U)) last = i;
        }
        int rejected = (ndraft > 0) && (last != ndraft - 1);
        s_last      = last;
        s_rejected  = rejected;
        s_prev      = prev;
        s_write_col = rejected ? (last + 1) : n;
    }
    __syncthreads();

    // Block-wide argmax over the recovery row (rejected requests only).
    // Key: (float_bits << 32) | (0xFFFFFFFF - idx). Softmax probs >= 0 so the
    // fp32 bit pattern is order-preserving; ties resolve to smallest index
    // (matches jnp.argmax).
    if (s_rejected) {
        int rec_row = s_prev + s_last + 1;
        rec_row = max(0, min(rec_row, NT - 1));
        const float* __restrict__ row = target_probs + (long long)rec_row * V;

        unsigned long long best = 0ull;
        if ((V & 3) == 0) {
            const float4* __restrict__ row4 = (const float4*)row;
            const int nv = V >> 2;
            for (int i = tid; i < nv; i += TPB) {
                float4 v = row4[i];
                unsigned base = (unsigned)i << 2;
                unsigned long long k;
                k = ((unsigned long long)__float_as_uint(v.x) << 32) | (0xFFFFFFFFu - base);
                if (k > best) best = k;
                k = ((unsigned long long)__float_as_uint(v.y) << 32) | (0xFFFFFFFFu - (base + 1));
                if (k > best) best = k;
                k = ((unsigned long long)__float_as_uint(v.z) << 32) | (0xFFFFFFFFu - (base + 2));
                if (k > best) best = k;
                k = ((unsigned long long)__float_as_uint(v.w) << 32) | (0xFFFFFFFFu - (base + 3));
                if (k > best) best = k;
            }
        } else {
            for (int i = tid; i < V; i += TPB) {
                unsigned long long k =
                    ((unsigned long long)__float_as_uint(row[i]) << 32) |
                    (0xFFFFFFFFu - (unsigned)i);
                if (k > best) best = k;
            }
        }

        #pragma unroll
        for (int off = 16; off > 0; off >>= 1) {
            unsigned long long o = __shfl_down_sync(0xFFFFFFFFu, best, off);
            if (o > best) best = o;
        }
        if ((tid & 31) == 0) s_warp[tid >> 5] = best;
        __syncthreads();

        if (tid < 32) {
            unsigned long long v = (tid < (TPB / 32)) ? s_warp[tid] : 0ull;
            #pragma unroll
            for (int off = 16; off > 0; off >>= 1) {
                unsigned long long o = __shfl_down_sync(0xFFFFFFFFu, v, off);
                if (o > v) v = o;
            }
            if (tid == 0)
                s_rec = (int)(0xFFFFFFFFu - (unsigned)(v & 0xFFFFFFFFull));
        }
        __syncthreads();
    }

    // Emit output row AS FLOAT (harness output dtype is float32; raw int -1
    // reinterpreted as float is NaN, which is what broke round 1).
    if (tid <= L) {
        int val = (tid < L && tid <= s_last) ? s_dids[tid] : -1;
        if (tid == s_write_col)
            val = s_rejected ? s_rec : bonus[b];
        out[b * (L + 1) + tid] = (float)val;
    }
}

extern "C" void kernel_launch(void* const* d_in, const int* in_sizes, int n_in,
                              void* d_out, int out_size) {
    const float* draft_probs     = (const float*)d_in[0];
    const float* target_probs    = (const float*)d_in[1];
    const float* uniform_probs   = (const float*)d_in[2];
    const int*   draft_token_ids = (const int*)  d_in[3];
    const int*   cu              = (const int*)  d_in[4];
    const int*   bonus           = (const int*)  d_in[5];
    float*       out             = (float*)d_out;

    const int NT = in_sizes[2];               // uniform_probs count
    const int V  = in_sizes[0] / NT;          // vocab
    const int B  = in_sizes[4];               // requests
    const int L  = out_size / B - 1;          // MAX_SPEC_LEN

    rejection_sample_kernel<<<B, TPB>>>(draft_probs, target_probs, uniform_probs,
                                        draft_token_ids, cu, bonus, out,
                                        V, NT, L);
}